// round 5
// baseline (speedup 1.0000x reference)
#include <cuda_runtime.h>

// FeatureContraction: out[b,c,w,x,v] = sum_i x[b,c,w,x,v,i] * attr[b,c,i]
// x: [16384, 768, 16] f32, attr: [16384, 16] f32, out: [16384, 768] f32.
// Pure HBM stream (~855 MB).
// R1: 1 bc/CTA, float4 loads  -> 127.2 us @ 86% DRAM, L1=71%.
// R2: 8 bc/CTA serial loop    -> 141 us  (REGRESSION, reverted).
// R3: +ldcs/stcs hints        -> 127.0 us (NEUTRAL).
// R4: LDG.256 (v8.f32)        -> 124.8 us @ 87.6% DRAM, L1=43%.  (best)
// R5: hoist x loads ABOVE attr smem staging + barrier — remove the ~600-cyc
//     serial head (attr LDG->STS->BAR) from in front of the x load issue.

#define BC_TOTAL 16384      // B*C
#define WXV      768        // X*Y*Y = 3*16*16
#define THREADS  256
#define PER_THR  (WXV / THREADS)   // 3

__device__ __forceinline__ void ldg256(const float* __restrict__ p,
                                       float4& lo, float4& hi)
{
    asm("ld.global.v8.f32 {%0,%1,%2,%3,%4,%5,%6,%7}, [%8];"
        : "=f"(lo.x), "=f"(lo.y), "=f"(lo.z), "=f"(lo.w),
          "=f"(hi.x), "=f"(hi.y), "=f"(hi.z), "=f"(hi.w)
        : "l"(p));
}

__global__ __launch_bounds__(THREADS)
void feature_contraction_kernel(const float* __restrict__ x,
                                const float4* __restrict__ attr,
                                float* __restrict__ out)
{
    const int bc = blockIdx.x;

    const float* __restrict__ xb = x + (size_t)bc * WXV * 16;

    // ---- Phase 1: issue all 6 independent LDG.256 FIRST (nothing blocks
    // them). Their ~600-cyc flight overlaps the attr staging below. ----
    float4 v[PER_THR][4];
    int    o[PER_THR];

#pragma unroll
    for (int k = 0; k < PER_THR; k++) {
        o[k] = k * THREADS + threadIdx.x;
        const float* __restrict__ xp = xb + (size_t)o[k] * 16;
        ldg256(xp,     v[k][0], v[k][1]);
        ldg256(xp + 8, v[k][2], v[k][3]);
    }

    // ---- Phase 2: stage attr[bc, 0:16] through smem (overlapped with the
    // x loads already in flight). ----
    __shared__ float4 s_a[4];
    if (threadIdx.x < 4) {
        s_a[threadIdx.x] = attr[(size_t)bc * 4 + threadIdx.x];
    }
    __syncthreads();

    const float4 a0 = s_a[0];
    const float4 a1 = s_a[1];
    const float4 a2 = s_a[2];
    const float4 a3 = s_a[3];

    // ---- Phase 3: FMA + store. ----
#pragma unroll
    for (int k = 0; k < PER_THR; k++) {
        float s;
        s  = v[k][0].x * a0.x;
        s += v[k][0].y * a0.y;
        s += v[k][0].z * a0.z;
        s += v[k][0].w * a0.w;
        s += v[k][1].x * a1.x;
        s += v[k][1].y * a1.y;
        s += v[k][1].z * a1.z;
        s += v[k][1].w * a1.w;
        s += v[k][2].x * a2.x;
        s += v[k][2].y * a2.y;
        s += v[k][2].z * a2.z;
        s += v[k][2].w * a2.w;
        s += v[k][3].x * a3.x;
        s += v[k][3].y * a3.y;
        s += v[k][3].z * a3.z;
        s += v[k][3].w * a3.w;
        out[(size_t)bc * WXV + o[k]] = s;
    }
}

extern "C" void kernel_launch(void* const* d_in, const int* in_sizes, int n_in,
                              void* d_out, int out_size)
{
    const float*  x    = (const float*)d_in[0];
    const float4* attr = (const float4*)d_in[1];
    float*        out  = (float*)d_out;

    feature_contraction_kernel<<<BC_TOTAL, THREADS>>>(x, attr, out);
}